// round 11
// baseline (speedup 1.0000x reference)
#include <cuda_runtime.h>
#include <cuda_fp16.h>
#include <cstdint>

// ImageWarped: trilinear sampling of [B,128,128,128,1] fp32 at [B,N,3] coords.
// B=2, N=2097152.
//
// R11 structure: per-batch phase pipeline to halve the gather working set:
//   pack(b0) -> sample(b0) -> pack(b1) -> sample(b1)
// During each sample phase only 32 MB of scratch is live and freshly written
// into L2, so scattered gathers hit L2 instead of round-tripping to DRAM.
// (Evict-last policy hints dropped: with a zero persisting-L2 carveout they
// were a no-op; grid/out keep evict-first streaming via __ldcs/__stcs.)
//
// Pack: scalar 8-load fp16 cube pack (fastest measured variant, R3/R9 form).
// Sample: ONE scattered 16B gather per sample, 2 samples/thread.
//
// fp16 quantization -> rel_err ~2.1e-4 (< 1e-3 gate, verified R3-R10).
// Out-of-range "+1" neighbors are weight-masked (exactly-zero fractional
// weights per the reference floor/ceil convention).

#define BATCH 2
#define NPTS  2097152
#define HVOX  (128 * 128 * 128)            // voxels per batch
#define VOXELS (BATCH * HVOX)
#define CLAMP_LO 0.001f
#define CLAMP_HI 126.999f

#define PACK_BLOCKS   (HVOX / 256)         // 8192 per batch
#define SAMPLE_BLOCKS (NPTS / 2 / 256)     // 4096 per batch (2 samples/thread)

__device__ uint4 g_packed[VOXELS];         // 64 MB scratch (32 MB live per phase)

__device__ __forceinline__ uint32_t pack_h2(float a, float b) {
    __half2 h = __floats2half2_rn(a, b);
    return *reinterpret_cast<uint32_t*>(&h);
}

__global__ void __launch_bounds__(256)
pack_kernel(const float* __restrict__ image, int vbase)
{
    const int idx = vbase + blockIdx.x * blockDim.x + threadIdx.x;
    const int z = idx & 127;
    const int y = (idx >> 7) & 127;
    const int x = (idx >> 14) & 127;
    const int dz = (z < 127) ? 1 : 0;
    const int dy = (y < 127) ? 128 : 0;
    const int dx = (x < 127) ? 16384 : 0;

    const float c111 = __ldg(image + idx);
    const float c112 = __ldg(image + idx + dz);
    const float c121 = __ldg(image + idx + dy);
    const float c122 = __ldg(image + idx + dy + dz);
    const float c211 = __ldg(image + idx + dx);
    const float c212 = __ldg(image + idx + dx + dz);
    const float c221 = __ldg(image + idx + dx + dy);
    const float c222 = __ldg(image + idx + dx + dy + dz);

    uint4 p;
    p.x = pack_h2(c111, c112);
    p.y = pack_h2(c121, c122);
    p.z = pack_h2(c211, c212);
    p.w = pack_h2(c221, c222);
    g_packed[idx] = p;                       // normal writeback: allocates in L2
}

__device__ __forceinline__ float sample_one(float gx, float gy, float gz, int base_b)
{
    const float x = fminf(fmaxf(gx * 128.0f, CLAMP_LO), CLAMP_HI);
    const float y = fminf(fmaxf(gy * 128.0f, CLAMP_LO), CLAMP_HI);
    const float z = fminf(fmaxf(gz * 128.0f, CLAMP_LO), CLAMP_HI);

    const float x1f = floorf(x), x2f = ceilf(x);
    const float y1f = floorf(y), y2f = ceilf(y);
    const float z1f = floorf(z), z2f = ceilf(z);

    const int cube = base_b + (((int)x1f) << 14) + (((int)y1f) << 7) + (int)z1f;
    const uint4 p = __ldg(&g_packed[cube]);   // one 16B scattered gather

    const float2 a1 = __half22float2(*reinterpret_cast<const __half2*>(&p.x)); // c111,c112
    const float2 a2 = __half22float2(*reinterpret_cast<const __half2*>(&p.y)); // c121,c122
    const float2 b1 = __half22float2(*reinterpret_cast<const __half2*>(&p.z)); // c211,c212
    const float2 b2 = __half22float2(*reinterpret_cast<const __half2*>(&p.w)); // c221,c222

    const float wx = x - x1f, wx2 = x2f - x;
    const float wy = y - y1f, wy2 = y2f - y;
    const float wz = z - z1f, wz2 = z2f - z;

    const float lerp_y1 = (b1.x * wx + a1.x * wx2) * wy2
                        + (b2.x * wx + a2.x * wx2) * wy;
    const float lerp_y2 = (b1.y * wx + a1.y * wx2) * wy2
                        + (b2.y * wx + a2.y * wx2) * wy;
    return lerp_y2 * wz + lerp_y1 * wz2;
}

__global__ void __launch_bounds__(256)
sample_kernel(const float* __restrict__ grid,
              float* __restrict__ out,
              int sample_base, int vbase)
{
    const int t = blockIdx.x * blockDim.x + threadIdx.x;     // 2 samples per thread
    const int s = sample_base + (t << 1);

    const float2* g = (const float2*)(grid + 3 * (size_t)s);
    const float2 q0 = __ldcs(g + 0);   // x0 y0
    const float2 q1 = __ldcs(g + 1);   // z0 x1
    const float2 q2 = __ldcs(g + 2);   // y1 z1

    float2 r;
    r.x = sample_one(q0.x, q0.y, q1.x, vbase);
    r.y = sample_one(q1.y, q2.x, q2.y, vbase);

    __stcs((float2*)(out + s), r);     // evict-first streaming store
}

extern "C" void kernel_launch(void* const* d_in, const int* in_sizes, int n_in,
                              void* d_out, int out_size)
{
    const float* image = (const float*)d_in[0];
    const float* grid  = (const float*)d_in[1];
    float* out = (float*)d_out;

    pack_kernel<<<PACK_BLOCKS, 256>>>(image, 0);
    sample_kernel<<<SAMPLE_BLOCKS, 256>>>(grid, out, 0, 0);
    pack_kernel<<<PACK_BLOCKS, 256>>>(image, HVOX);
    sample_kernel<<<SAMPLE_BLOCKS, 256>>>(grid, out, NPTS, HVOX);
}

// round 12
// speedup vs baseline: 1.0948x; 1.0948x over previous
#include <cuda_runtime.h>
#include <cuda_fp16.h>
#include <cstdint>

// ImageWarped: trilinear sampling of [B,128,128,128,1] fp32 at [B,N,3] coords.
// B=2, N=2097152.
//
// R12: cross-batch overlap with the FAST scalar pack (R10 showed ~6us of
// real pack/sample overlap but used the slow x-pair pack):
//   K1: pack(b0)                      8192 blocks   (~7us)
//   K2: pack(b1) + sample(b0) 2:1 interleaved by blockIdx%3  (~17us)
//   K3: sample(b1)                    4096 blocks   (~15us)
// Pack: scalar 8-load fp16 cube per voxel -> uint4 (evict-last hint).
// Sample: ONE scattered 16B gather/sample (evict-last), 2 samples/thread,
// grid/out evict-first streaming.
//
// fp16 quantization -> rel_err ~2.1e-4 (< 1e-3 gate, verified R3-R11).
// Out-of-range "+1" neighbors are weight-masked (exactly-zero fractional
// weights per the reference floor/ceil convention).

#define BATCH 2
#define NPTS  2097152
#define HVOX  (128 * 128 * 128)
#define VOXELS (BATCH * HVOX)
#define CLAMP_LO 0.001f
#define CLAMP_HI 126.999f

#define PACK_BLOCKS   (HVOX / 256)         // 8192 per batch
#define SAMPLE_BLOCKS (NPTS / 2 / 256)     // 4096 per batch
#define MID_BLOCKS    (PACK_BLOCKS + SAMPLE_BLOCKS)  // 12288

__device__ uint4 g_packed[VOXELS];         // 64 MB scratch

__device__ __forceinline__ uint32_t pack_h2(float a, float b) {
    __half2 h = __floats2half2_rn(a, b);
    return *reinterpret_cast<uint32_t*>(&h);
}

__device__ __forceinline__ uint64_t mk_evict_last_policy() {
    uint64_t pol;
    asm("createpolicy.fractional.L2::evict_last.b64 %0, 1.0;" : "=l"(pol));
    return pol;
}

__device__ __forceinline__ void st_hint_v4(uint4* p, uint4 v, uint64_t pol) {
    asm volatile("st.global.L2::cache_hint.v4.b32 [%0], {%1,%2,%3,%4}, %5;"
                 :: "l"(p), "r"(v.x), "r"(v.y), "r"(v.z), "r"(v.w), "l"(pol)
                 : "memory");
}

__device__ __forceinline__ uint4 ld_nc_hint_v4(const uint4* p, uint64_t pol) {
    uint4 v;
    asm volatile("ld.global.nc.L2::cache_hint.v4.b32 {%0,%1,%2,%3}, [%4], %5;"
                 : "=r"(v.x), "=r"(v.y), "=r"(v.z), "=r"(v.w)
                 : "l"(p), "l"(pol));
    return v;
}

// Scalar pack of one voxel (fastest measured variant).
__device__ __forceinline__ void pack_voxel(const float* __restrict__ image,
                                           int idx, uint64_t pol)
{
    const int z = idx & 127;
    const int y = (idx >> 7) & 127;
    const int x = (idx >> 14) & 127;
    const int dz = (z < 127) ? 1 : 0;
    const int dy = (y < 127) ? 128 : 0;
    const int dx = (x < 127) ? 16384 : 0;

    const float c111 = __ldg(image + idx);
    const float c112 = __ldg(image + idx + dz);
    const float c121 = __ldg(image + idx + dy);
    const float c122 = __ldg(image + idx + dy + dz);
    const float c211 = __ldg(image + idx + dx);
    const float c212 = __ldg(image + idx + dx + dz);
    const float c221 = __ldg(image + idx + dx + dy);
    const float c222 = __ldg(image + idx + dx + dy + dz);

    uint4 p;
    p.x = pack_h2(c111, c112);
    p.y = pack_h2(c121, c122);
    p.z = pack_h2(c211, c212);
    p.w = pack_h2(c221, c222);
    st_hint_v4(&g_packed[idx], p, pol);
}

__device__ __forceinline__ float sample_one(float gx, float gy, float gz,
                                            int base_b, uint64_t pol)
{
    const float x = fminf(fmaxf(gx * 128.0f, CLAMP_LO), CLAMP_HI);
    const float y = fminf(fmaxf(gy * 128.0f, CLAMP_LO), CLAMP_HI);
    const float z = fminf(fmaxf(gz * 128.0f, CLAMP_LO), CLAMP_HI);

    const float x1f = floorf(x), x2f = ceilf(x);
    const float y1f = floorf(y), y2f = ceilf(y);
    const float z1f = floorf(z), z2f = ceilf(z);

    const int cube = base_b + (((int)x1f) << 14) + (((int)y1f) << 7) + (int)z1f;
    const uint4 p = ld_nc_hint_v4(&g_packed[cube], pol);

    const float2 a1 = __half22float2(*reinterpret_cast<const __half2*>(&p.x)); // c111,c112
    const float2 a2 = __half22float2(*reinterpret_cast<const __half2*>(&p.y)); // c121,c122
    const float2 b1 = __half22float2(*reinterpret_cast<const __half2*>(&p.z)); // c211,c212
    const float2 b2 = __half22float2(*reinterpret_cast<const __half2*>(&p.w)); // c221,c222

    const float wx = x - x1f, wx2 = x2f - x;
    const float wy = y - y1f, wy2 = y2f - y;
    const float wz = z - z1f, wz2 = z2f - z;

    const float lerp_y1 = (b1.x * wx + a1.x * wx2) * wy2
                        + (b2.x * wx + a2.x * wx2) * wy;
    const float lerp_y2 = (b1.y * wx + a1.y * wx2) * wy2
                        + (b2.y * wx + a2.y * wx2) * wy;
    return lerp_y2 * wz + lerp_y1 * wz2;
}

__device__ __forceinline__ void sample_pair(const float* __restrict__ grid,
                                            float* __restrict__ out,
                                            int tprime, int sample_base,
                                            int base_b, uint64_t pol)
{
    const int s = sample_base + (tprime << 1);
    const float2* g = (const float2*)(grid + 3 * (size_t)s);
    const float2 q0 = __ldcs(g + 0);   // x0 y0
    const float2 q1 = __ldcs(g + 1);   // z0 x1
    const float2 q2 = __ldcs(g + 2);   // y1 z1

    float2 r;
    r.x = sample_one(q0.x, q0.y, q1.x, base_b, pol);
    r.y = sample_one(q1.y, q2.x, q2.y, base_b, pol);
    __stcs((float2*)(out + s), r);
}

__global__ void __launch_bounds__(256)
pack0_kernel(const float* __restrict__ image)
{
    const uint64_t pol = mk_evict_last_policy();
    pack_voxel(image, blockIdx.x * 256 + threadIdx.x, pol);          // batch 0
}

// 2:1 interleave: blockIdx%3 in {0,1} -> pack batch1; ==2 -> sample batch0.
__global__ void __launch_bounds__(256)
mid_kernel(const float* __restrict__ image,
           const float* __restrict__ grid,
           float* __restrict__ out)
{
    const uint64_t pol = mk_evict_last_policy();
    const int grp = blockIdx.x / 3;
    const int rem = blockIdx.x % 3;
    if (rem < 2) {
        const int pb = grp * 2 + rem;                                 // [0,8192)
        pack_voxel(image, HVOX + pb * 256 + threadIdx.x, pol);        // batch 1
    } else {
        sample_pair(grid, out, grp * 256 + threadIdx.x, 0, 0, pol);   // batch 0
    }
}

__global__ void __launch_bounds__(256)
sample1_kernel(const float* __restrict__ grid,
               float* __restrict__ out)
{
    const uint64_t pol = mk_evict_last_policy();
    const int tprime = blockIdx.x * 256 + threadIdx.x;
    sample_pair(grid, out, tprime, NPTS, HVOX, pol);                  // batch 1
}

extern "C" void kernel_launch(void* const* d_in, const int* in_sizes, int n_in,
                              void* d_out, int out_size)
{
    const float* image = (const float*)d_in[0];
    const float* grid  = (const float*)d_in[1];
    float* out = (float*)d_out;

    pack0_kernel<<<PACK_BLOCKS, 256>>>(image);
    mid_kernel<<<MID_BLOCKS, 256>>>(image, grid, out);
    sample1_kernel<<<SAMPLE_BLOCKS, 256>>>(grid, out);
}

// round 13
// speedup vs baseline: 1.1330x; 1.0349x over previous
#include <cuda_runtime.h>
#include <cuda_fp16.h>
#include <cstdint>

// ImageWarped: trilinear sampling of [B,128,128,128,1] fp32 at [B,N,3] coords.
// B=2, N=2097152.
//
// R13 = R9 (best, 43.5us) + ILP-2 pack: one thread packs the SAME (x,y,z)
// voxel in BOTH batches -> index math shared, 16 independent loads in
// flight, both stores warp-coalesced, ALU/voxel halved.
//
// Pack: 2x2x2 fp16 corner cube per voxel -> uint4 (evict-last L2 hint).
// Sample: ONE scattered 16B gather per sample (evict-last), 2 samples/
//   thread, grid/out evict-first streaming. Sample is at the L1tex
//   within-LDG replay floor (~30us) — structurally optimal.
//
// fp16 quantization -> rel_err ~2.1e-4 (< 1e-3 gate, verified R3-R12).
// Out-of-range "+1" neighbors are weight-masked (exactly-zero fractional
// weights per the reference floor/ceil convention).

#define BATCH 2
#define NPTS  2097152
#define HVOX  (128 * 128 * 128)            // voxels per batch
#define VOXELS (BATCH * HVOX)
#define CLAMP_LO 0.001f
#define CLAMP_HI 126.999f

#define PACK_BLOCKS   (HVOX / 256)         // 8192 (each thread: 2 voxels)
#define SAMPLE_BLOCKS (BATCH * NPTS / 2 / 256)  // 8192 (2 samples/thread)

__device__ uint4 g_packed[VOXELS];         // 64 MB scratch

__device__ __forceinline__ uint32_t pack_h2(float a, float b) {
    __half2 h = __floats2half2_rn(a, b);
    return *reinterpret_cast<uint32_t*>(&h);
}

__device__ __forceinline__ uint64_t mk_evict_last_policy() {
    uint64_t pol;
    asm("createpolicy.fractional.L2::evict_last.b64 %0, 1.0;" : "=l"(pol));
    return pol;
}

__device__ __forceinline__ void st_hint_v4(uint4* p, uint4 v, uint64_t pol) {
    asm volatile("st.global.L2::cache_hint.v4.b32 [%0], {%1,%2,%3,%4}, %5;"
                 :: "l"(p), "r"(v.x), "r"(v.y), "r"(v.z), "r"(v.w), "l"(pol)
                 : "memory");
}

__device__ __forceinline__ uint4 ld_nc_hint_v4(const uint4* p, uint64_t pol) {
    uint4 v;
    asm volatile("ld.global.nc.L2::cache_hint.v4.b32 {%0,%1,%2,%3}, [%4], %5;"
                 : "=r"(v.x), "=r"(v.y), "=r"(v.z), "=r"(v.w)
                 : "l"(p), "l"(pol));
    return v;
}

__global__ void __launch_bounds__(256)
pack_kernel(const float* __restrict__ image)
{
    const uint64_t pol = mk_evict_last_policy();
    const int idx = blockIdx.x * blockDim.x + threadIdx.x;   // batch-0 voxel
    const int z = idx & 127;
    const int y = (idx >> 7) & 127;
    const int x = idx >> 14;                                 // [0,128)
    const int dz = (z < 127) ? 1 : 0;
    const int dy = (y < 127) ? 128 : 0;
    const int dx = (x < 127) ? 16384 : 0;

    const int j = idx + HVOX;                                // batch-1 voxel

    // Batch 0 cube (8 loads) and batch 1 cube (8 loads) — independent chains.
    const float a111 = __ldg(image + idx);
    const float a112 = __ldg(image + idx + dz);
    const float a121 = __ldg(image + idx + dy);
    const float a122 = __ldg(image + idx + dy + dz);
    const float a211 = __ldg(image + idx + dx);
    const float a212 = __ldg(image + idx + dx + dz);
    const float a221 = __ldg(image + idx + dx + dy);
    const float a222 = __ldg(image + idx + dx + dy + dz);

    const float b111 = __ldg(image + j);
    const float b112 = __ldg(image + j + dz);
    const float b121 = __ldg(image + j + dy);
    const float b122 = __ldg(image + j + dy + dz);
    const float b211 = __ldg(image + j + dx);
    const float b212 = __ldg(image + j + dx + dz);
    const float b221 = __ldg(image + j + dx + dy);
    const float b222 = __ldg(image + j + dx + dy + dz);

    uint4 pa, pb;
    pa.x = pack_h2(a111, a112);
    pa.y = pack_h2(a121, a122);
    pa.z = pack_h2(a211, a212);
    pa.w = pack_h2(a221, a222);
    pb.x = pack_h2(b111, b112);
    pb.y = pack_h2(b121, b122);
    pb.z = pack_h2(b211, b212);
    pb.w = pack_h2(b221, b222);

    st_hint_v4(&g_packed[idx], pa, pol);   // both warp-coalesced
    st_hint_v4(&g_packed[j],   pb, pol);
}

__device__ __forceinline__ float sample_one(float gx, float gy, float gz,
                                            int base_b, uint64_t pol)
{
    const float x = fminf(fmaxf(gx * 128.0f, CLAMP_LO), CLAMP_HI);
    const float y = fminf(fmaxf(gy * 128.0f, CLAMP_LO), CLAMP_HI);
    const float z = fminf(fmaxf(gz * 128.0f, CLAMP_LO), CLAMP_HI);

    const float x1f = floorf(x), x2f = ceilf(x);
    const float y1f = floorf(y), y2f = ceilf(y);
    const float z1f = floorf(z), z2f = ceilf(z);

    const int cube = base_b + (((int)x1f) << 14) + (((int)y1f) << 7) + (int)z1f;
    const uint4 p = ld_nc_hint_v4(&g_packed[cube], pol);

    const float2 a1 = __half22float2(*reinterpret_cast<const __half2*>(&p.x)); // c111,c112
    const float2 a2 = __half22float2(*reinterpret_cast<const __half2*>(&p.y)); // c121,c122
    const float2 b1 = __half22float2(*reinterpret_cast<const __half2*>(&p.z)); // c211,c212
    const float2 b2 = __half22float2(*reinterpret_cast<const __half2*>(&p.w)); // c221,c222

    const float wx = x - x1f, wx2 = x2f - x;
    const float wy = y - y1f, wy2 = y2f - y;
    const float wz = z - z1f, wz2 = z2f - z;

    const float lerp_y1 = (b1.x * wx + a1.x * wx2) * wy2
                        + (b2.x * wx + a2.x * wx2) * wy;
    const float lerp_y2 = (b1.y * wx + a1.y * wx2) * wy2
                        + (b2.y * wx + a2.y * wx2) * wy;
    return lerp_y2 * wz + lerp_y1 * wz2;
}

__global__ void __launch_bounds__(256)
trilinear_kernel(const float* __restrict__ grid,
                 float* __restrict__ out)
{
    const uint64_t pol = mk_evict_last_policy();
    const int t = blockIdx.x * blockDim.x + threadIdx.x;     // 2 samples/thread
    const int s = t << 1;
    const int base_b = (s >> 21) << 21;                      // batch base

    const float2* g = (const float2*)(grid + 3 * (size_t)s);
    const float2 q0 = __ldcs(g + 0);   // x0 y0
    const float2 q1 = __ldcs(g + 1);   // z0 x1
    const float2 q2 = __ldcs(g + 2);   // y1 z1

    float2 r;
    r.x = sample_one(q0.x, q0.y, q1.x, base_b, pol);
    r.y = sample_one(q1.y, q2.x, q2.y, base_b, pol);

    __stcs((float2*)(out + s), r);     // evict-first streaming store
}

extern "C" void kernel_launch(void* const* d_in, const int* in_sizes, int n_in,
                              void* d_out, int out_size)
{
    const float* image = (const float*)d_in[0];
    const float* grid  = (const float*)d_in[1];
    float* out = (float*)d_out;

    pack_kernel<<<PACK_BLOCKS, 256>>>(image);
    trilinear_kernel<<<SAMPLE_BLOCKS, 256>>>(grid, out);
}